// round 3
// baseline (speedup 1.0000x reference)
#include <cuda_runtime.h>

#define NN 768
#define CC 64
#define C2 128

// ---------------- scratch (device globals; no allocation allowed) -------------
__device__ float g_q[CC * NN], g_k[CC * NN], g_v[CC * NN];
__device__ float g_r1[C2 * NN];                 // relu(norm(q|k)) stacked
__device__ float g_A[C2 * NN], g_B[C2 * NN];    // separable conv1 outputs
__device__ float g_Sq[NN], g_Sk[NN];            // shortcut row/col terms
__device__ float g_stat[4 * C2];                // meanA | varA | meanB | varB
__device__ float g_P[NN * NN];                  // logits scratch
__device__ float g_avp[4 * CC * NN];            // split-k partials of score@v^T
__device__ float g_av2[CC * NN];                // after mh conv
__device__ float g_g1[C2 * NN];                 // cat conv1 output
__device__ float g_gstat[2 * C2];               // mean | var of g1 rows

// ---------------- reductions --------------------------------------------------
__device__ __forceinline__ float2 block_reduce_sum2(float a, float b) {
    __shared__ float sA[8], sB[8];
    __syncthreads();
#pragma unroll
    for (int o = 16; o > 0; o >>= 1) {
        a += __shfl_down_sync(0xffffffffu, a, o);
        b += __shfl_down_sync(0xffffffffu, b, o);
    }
    int lane = threadIdx.x & 31, w = threadIdx.x >> 5;
    if (lane == 0) { sA[w] = a; sB[w] = b; }
    __syncthreads();
    if (threadIdx.x == 0) {
        float ra = 0.f, rb = 0.f;
        int nw = blockDim.x >> 5;
        for (int i = 0; i < nw; i++) { ra += sA[i]; rb += sB[i]; }
        sA[0] = ra; sB[0] = rb;
    }
    __syncthreads();
    return make_float2(sA[0], sB[0]);
}

__device__ __forceinline__ float block_reduce_max(float a) {
    __shared__ float sM[8];
    __syncthreads();
#pragma unroll
    for (int o = 16; o > 0; o >>= 1)
        a = fmaxf(a, __shfl_down_sync(0xffffffffu, a, o));
    int lane = threadIdx.x & 31, w = threadIdx.x >> 5;
    if (lane == 0) sM[w] = a;
    __syncthreads();
    if (threadIdx.x == 0) {
        float r = sM[0];
        int nw = blockDim.x >> 5;
        for (int i = 1; i < nw; i++) r = fmaxf(r, sM[i]);
        sM[0] = r;
    }
    __syncthreads();
    return sM[0];
}

// ---------------- K1: q,k,v = W @ desc + b ------------------------------------
__global__ void k_qkv(const float* __restrict__ desc1, const float* __restrict__ desc2,
                      const float* __restrict__ qw, const float* __restrict__ qb,
                      const float* __restrict__ kw, const float* __restrict__ kb,
                      const float* __restrict__ vw, const float* __restrict__ vb) {
    __shared__ float Ws[64 * 64];
    __shared__ float Xs[64 * 64];
    int which = blockIdx.y;
    const float* W    = which == 0 ? qw : (which == 1 ? kw : vw);
    const float* bias = which == 0 ? qb : (which == 1 ? kb : vb);
    const float* X    = (which == 0) ? desc1 : desc2;
    float* out        = which == 0 ? g_q : (which == 1 ? g_k : g_v);
    int n0 = blockIdx.x * 64;
    int tid = threadIdx.x;
    for (int i = tid; i < 4096; i += 256) {
        Ws[i] = W[i];
        Xs[i] = X[(i >> 6) * NN + n0 + (i & 63)];
    }
    __syncthreads();
    int c = tid >> 2, nb = tid & 3;
    float acc[16];
    float b0 = bias[c];
#pragma unroll
    for (int j = 0; j < 16; j++) acc[j] = b0;
    for (int i = 0; i < 64; i++) {
        float w = Ws[c * 64 + i];
#pragma unroll
        for (int j = 0; j < 16; j++)
            acc[j] = fmaf(w, Xs[i * 64 + nb + 4 * j], acc[j]);
    }
#pragma unroll
    for (int j = 0; j < 16; j++) out[c * NN + n0 + nb + 4 * j] = acc[j];
}

// ---------------- K2: inorm+bnorm1+relu on q/k channels -----------------------
__global__ void k_norm1(const float* __restrict__ bn1g, const float* __restrict__ bn1b) {
    __shared__ float xs[NN];
    int ch = blockIdx.x;
    const float* src = ch < CC ? g_q + ch * NN : g_k + (ch - CC) * NN;
    int tid = threadIdx.x;
    float s = 0.f, ss = 0.f;
    for (int i = tid; i < NN; i += 256) { float v = src[i]; xs[i] = v; s += v; ss += v * v; }
    float2 r = block_reduce_sum2(s, ss);
    float mean = r.x * (1.f / NN);
    float var  = r.y * (1.f / NN) - mean * mean;
    float rin = rsqrtf(var + 1e-3f);                     // inorm2d eps
    float s2  = rsqrtf(var * rin * rin + 1e-5f);         // bnorm2d eps
    float a = rin * s2 * bn1g[ch];
    float b = bn1b[ch] - mean * a;
    for (int i = tid; i < NN; i += 256)
        g_r1[ch * NN + i] = fmaxf(fmaf(a, xs[i], b), 0.f);
}

// ---------------- K3: A = W1[:, :64] @ r1q ; B = W1[:, 64:] @ r1k ; shot ------
__global__ void k_AB(const float* __restrict__ w1, const float* __restrict__ shotw) {
    int g = blockIdx.y;
    int n0 = blockIdx.x * 64;
    int tid = threadIdx.x;
    if (g == 2) {  // shortcut: Sq[n] = sum_c sw[c] q[c,n]; Sk[m] = sum_c sw[64+c] k[c,m]
        if (tid < 128) {
            int half = tid >> 6;
            int col  = tid & 63;
            const float* src = half ? g_k : g_q;
            const float* w   = shotw + half * 64;
            float s = 0.f;
            for (int c2 = 0; c2 < 64; c2++)
                s = fmaf(w[c2], src[c2 * NN + n0 + col], s);
            (half ? g_Sk : g_Sq)[n0 + col] = s;
        }
        return;
    }
    __shared__ float Wh[128 * 64];
    __shared__ float Xt[64 * 64];
    const float* r1src = g_r1 + g * 64 * NN;
    for (int i = tid; i < 8192; i += 256)
        Wh[i] = w1[(i >> 6) * 128 + g * 64 + (i & 63)];
    for (int i = tid; i < 4096; i += 256)
        Xt[i] = r1src[(i >> 6) * NN + n0 + (i & 63)];
    __syncthreads();
    int cg = tid & 15, orow = (tid >> 4) * 8;
    int col0 = cg * 4;
    float acc[8][4];
#pragma unroll
    for (int a = 0; a < 8; a++)
#pragma unroll
        for (int b = 0; b < 4; b++) acc[a][b] = 0.f;
    for (int i = 0; i < 64; i++) {
        float4 x = *(float4*)&Xt[i * 64 + col0];
#pragma unroll
        for (int oo = 0; oo < 8; oo++) {
            float w = Wh[(orow + oo) * 64 + i];
            acc[oo][0] = fmaf(w, x.x, acc[oo][0]);
            acc[oo][1] = fmaf(w, x.y, acc[oo][1]);
            acc[oo][2] = fmaf(w, x.z, acc[oo][2]);
            acc[oo][3] = fmaf(w, x.w, acc[oo][3]);
        }
    }
    float* out = g ? g_B : g_A;
#pragma unroll
    for (int oo = 0; oo < 8; oo++)
        *(float4*)&out[(orow + oo) * NN + n0 + col0] =
            make_float4(acc[oo][0], acc[oo][1], acc[oo][2], acc[oo][3]);
}

// ---------------- K4: per-row stats of A and B --------------------------------
__global__ void k_rowstat() {
    int r = blockIdx.x;
    const float* src = r < C2 ? g_A + r * NN : g_B + (r - C2) * NN;
    int tid = threadIdx.x;
    float s = 0.f, ss = 0.f;
    for (int i = tid; i < NN; i += 256) { float v = src[i]; s += v; ss += v * v; }
    float2 red = block_reduce_sum2(s, ss);
    if (tid == 0) {
        float mean = red.x * (1.f / NN);
        float var  = red.y * (1.f / NN) - mean * mean;
        if (r < C2) { g_stat[r] = mean; g_stat[C2 + r] = var; }
        else        { g_stat[2 * C2 + (r - C2)] = mean; g_stat[3 * C2 + (r - C2)] = var; }
    }
}

// ---------------- K5: heavy — P[n,m] = sum_o w2[o]*relu(A''+B') + row + col ---
__global__ void k_heavy(const float* __restrict__ bn2g, const float* __restrict__ bn2b,
                        const float* __restrict__ w2,   const float* __restrict__ b2,
                        const float* __restrict__ shotb) {
    extern __shared__ float sm[];
    float* As   = sm;             // 128*64
    float* Bs   = sm + 8192;      // 128*64
    float* tO   = sm + 16384;     // 128
    float* shA  = tO + 128;
    float* shB  = shA + 128;
    float* w2s  = shB + 128;
    float* rowc = w2s + 128;      // 64
    float* colc = rowc + 64;      // 64
    int tid = threadIdx.x;
    int n0 = blockIdx.x * 64, m0 = blockIdx.y * 64;
    if (tid < 128) {
        int o = tid;
        float mA = g_stat[o], vA = g_stat[C2 + o];
        float mB = g_stat[2 * C2 + o], vB = g_stat[3 * C2 + o];
        float var = vA + vB;                          // exact for separable field
        float r2 = rsqrtf(var + 1e-3f);
        float t = r2 * rsqrtf(var * r2 * r2 + 1e-5f) * bn2g[o];
        tO[o]  = t;
        shA[o] = bn2b[o] - mA * t;
        shB[o] = -mB * t;
        w2s[o] = w2[o];
    } else if (tid < 192) {
        int i = tid - 128;
        rowc[i] = g_Sq[n0 + i] + b2[0] + shotb[0];
    } else {
        int i = tid - 192;
        colc[i] = g_Sk[m0 + i];
    }
    __syncthreads();
    for (int idx = tid; idx < 2048; idx += 256) {
        int o = idx >> 4, c = (idx & 15) * 4;
        float t = tO[o];
        float sA = shA[o], sB = shB[o];
        float4 a = *(const float4*)&g_A[o * NN + n0 + c];
        a.x = fmaf(a.x, t, sA); a.y = fmaf(a.y, t, sA);
        a.z = fmaf(a.z, t, sA); a.w = fmaf(a.w, t, sA);
        *(float4*)&As[o * 64 + c] = a;
        float4 b = *(const float4*)&g_B[o * NN + m0 + c];
        b.x = fmaf(b.x, t, sB); b.y = fmaf(b.y, t, sB);
        b.z = fmaf(b.z, t, sB); b.w = fmaf(b.w, t, sB);
        *(float4*)&Bs[o * 64 + c] = b;
    }
    __syncthreads();
    int tn = tid & 15, tm = tid >> 4;
    int na = tn * 4, ma = tm * 4;
    float acc[16];
#pragma unroll
    for (int i = 0; i < 16; i++) acc[i] = 0.f;
#pragma unroll 2
    for (int o = 0; o < 128; o++) {
        float4 af = *(float4*)&As[o * 64 + na];
        float4 bf = *(float4*)&Bs[o * 64 + ma];
        float w = w2s[o];
        float av[4] = {af.x, af.y, af.z, af.w};
        float bv[4] = {bf.x, bf.y, bf.z, bf.w};
#pragma unroll
        for (int i = 0; i < 4; i++)
#pragma unroll
            for (int j = 0; j < 4; j++)
                acc[i * 4 + j] = fmaf(w, fmaxf(av[i] + bv[j], 0.f), acc[i * 4 + j]);
    }
#pragma unroll
    for (int i = 0; i < 4; i++) {
        float rc = rowc[na + i];
        float4 o4;
        o4.x = acc[i * 4 + 0] + rc + colc[ma + 0];
        o4.y = acc[i * 4 + 1] + rc + colc[ma + 1];
        o4.z = acc[i * 4 + 2] + rc + colc[ma + 2];
        o4.w = acc[i * 4 + 3] + rc + colc[ma + 3];
        *(float4*)&g_P[(n0 + na + i) * NN + m0 + ma] = o4;
    }
}

// ---------------- K6: row softmax --------------------------------------------
__global__ void k_softmax(float* __restrict__ score) {
    __shared__ float row[NN];
    int n = blockIdx.x;
    int tid = threadIdx.x;
    float mx = -1e30f;
    for (int i = tid; i < NN; i += 256) { float v = g_P[n * NN + i]; row[i] = v; mx = fmaxf(mx, v); }
    mx = block_reduce_max(mx);
    float s = 0.f;
    for (int i = tid; i < NN; i += 256) { float e = expf(row[i] - mx); row[i] = e; s += e; }
    float2 rr = block_reduce_sum2(s, 0.f);
    float inv = 1.f / rr.x;
    for (int i = tid; i < NN; i += 256) score[n * NN + i] = row[i] * inv;
}

// ---------------- K7: av[d,n] = sum_m score[n,m] v[d,m] (split-k partials) ----
__global__ void k_av(const float* __restrict__ score) {
    extern __shared__ float sm[];
    float* Ss = sm;                 // 16*193
    float* Vs = sm + 16 * 193;      // 64*193
    int n0 = blockIdx.x * 16;
    int m0 = blockIdx.y * 192;
    int tid = threadIdx.x;
    for (int idx = tid; idx < 16 * 192; idx += 256) {
        int n = idx / 192, m = idx - n * 192;
        Ss[n * 193 + m] = score[(n0 + n) * NN + m0 + m];
    }
    for (int idx = tid; idx < 64 * 192; idx += 256) {
        int d = idx / 192, m = idx - d * 192;
        Vs[d * 193 + m] = g_v[d * NN + m0 + m];
    }
    __syncthreads();
    int nl = tid & 15, dg = tid >> 4;
    float a0 = 0.f, a1 = 0.f, a2 = 0.f, a3 = 0.f;
    const float* sp = &Ss[nl * 193];
    const float* vp = &Vs[dg * 4 * 193];
    for (int m = 0; m < 192; m++) {
        float s = sp[m];
        a0 = fmaf(vp[m], s, a0);
        a1 = fmaf(vp[193 + m], s, a1);
        a2 = fmaf(vp[2 * 193 + m], s, a2);
        a3 = fmaf(vp[3 * 193 + m], s, a3);
    }
    int d0 = dg * 4;
    float* out = g_avp + blockIdx.y * CC * NN;
    out[(d0 + 0) * NN + n0 + nl] = a0;
    out[(d0 + 1) * NN + n0 + nl] = a1;
    out[(d0 + 2) * NN + n0 + nl] = a2;
    out[(d0 + 3) * NN + n0 + nl] = a3;
}

// ---------------- K8a: reduce partials + mh conv ------------------------------
__global__ void k_mh(const float* __restrict__ mhw, const float* __restrict__ mhb) {
    __shared__ float Wm[64 * 64];
    __shared__ float avt[64 * 32];
    int n0 = blockIdx.x * 32;
    int tid = threadIdx.x;
    for (int i = tid; i < 4096; i += 256) Wm[i] = mhw[i];
    for (int i = tid; i < 2048; i += 256) {
        int d = i >> 5, c = i & 31;
        float v = 0.f;
#pragma unroll
        for (int s = 0; s < 4; s++) v += g_avp[(s * 64 + d) * NN + n0 + c];
        avt[d * 32 + c] = v;
    }
    __syncthreads();
    int colg = tid & 7, crow = (tid >> 3) * 2;
    int col0 = colg * 4;
    float a0[4], a1[4];
    float b0v = mhb[crow], b1v = mhb[crow + 1];
#pragma unroll
    for (int j = 0; j < 4; j++) { a0[j] = b0v; a1[j] = b1v; }
    for (int d = 0; d < 64; d++) {
        float4 x = *(float4*)&avt[d * 32 + col0];
        float w0 = Wm[crow * 64 + d], w1 = Wm[(crow + 1) * 64 + d];
        a0[0] = fmaf(w0, x.x, a0[0]); a0[1] = fmaf(w0, x.y, a0[1]);
        a0[2] = fmaf(w0, x.z, a0[2]); a0[3] = fmaf(w0, x.w, a0[3]);
        a1[0] = fmaf(w1, x.x, a1[0]); a1[1] = fmaf(w1, x.y, a1[1]);
        a1[2] = fmaf(w1, x.z, a1[2]); a1[3] = fmaf(w1, x.w, a1[3]);
    }
    *(float4*)&g_av2[crow * NN + n0 + col0]       = make_float4(a0[0], a0[1], a0[2], a0[3]);
    *(float4*)&g_av2[(crow + 1) * NN + n0 + col0] = make_float4(a1[0], a1[1], a1[2], a1[3]);
}

// ---------------- K8b: g1 = cat_w1 @ [desc1; av2] + cat_b1 --------------------
__global__ void k_cat1(const float* __restrict__ d1, const float* __restrict__ w1c,
                       const float* __restrict__ b1c) {
    extern __shared__ float sm[];
    float* W  = sm;            // 64*128
    float* Xc = sm + 8192;     // 128*32
    int n0 = blockIdx.x * 32;
    int oh = blockIdx.y;
    int tid = threadIdx.x;
    for (int i = tid; i < 8192; i += 256)
        W[i] = w1c[(oh * 64 + (i >> 7)) * 128 + (i & 127)];
    for (int i = tid; i < 4096; i += 256) {
        int j = i >> 5, c = i & 31;
        Xc[j * 32 + c] = j < 64 ? d1[j * NN + n0 + c] : g_av2[(j - 64) * NN + n0 + c];
    }
    __syncthreads();
    int colg = tid & 7, orow = (tid >> 3) * 2;
    int col0 = colg * 4;
    float a0[4], a1[4];
    float bb0 = b1c[oh * 64 + orow], bb1 = b1c[oh * 64 + orow + 1];
#pragma unroll
    for (int j = 0; j < 4; j++) { a0[j] = bb0; a1[j] = bb1; }
    for (int j = 0; j < 128; j++) {
        float4 x = *(float4*)&Xc[j * 32 + col0];
        float w0 = W[orow * 128 + j], w1 = W[(orow + 1) * 128 + j];
        a0[0] = fmaf(w0, x.x, a0[0]); a0[1] = fmaf(w0, x.y, a0[1]);
        a0[2] = fmaf(w0, x.z, a0[2]); a0[3] = fmaf(w0, x.w, a0[3]);
        a1[0] = fmaf(w1, x.x, a1[0]); a1[1] = fmaf(w1, x.y, a1[1]);
        a1[2] = fmaf(w1, x.z, a1[2]); a1[3] = fmaf(w1, x.w, a1[3]);
    }
    *(float4*)&g_g1[(oh * 64 + orow) * NN + n0 + col0]     = make_float4(a0[0], a0[1], a0[2], a0[3]);
    *(float4*)&g_g1[(oh * 64 + orow + 1) * NN + n0 + col0] = make_float4(a1[0], a1[1], a1[2], a1[3]);
}

// ---------------- K8c: stats of g1 rows ---------------------------------------
__global__ void k_gstat() {
    int r = blockIdx.x;
    const float* src = g_g1 + r * NN;
    int tid = threadIdx.x;
    float s = 0.f, ss = 0.f;
    for (int i = tid; i < NN; i += 256) { float v = src[i]; s += v; ss += v * v; }
    float2 red = block_reduce_sum2(s, ss);
    if (tid == 0) {
        float mean = red.x * (1.f / NN);
        g_gstat[r] = mean;
        g_gstat[C2 + r] = red.y * (1.f / NN) - mean * mean;
    }
}

// ---------------- K8d: out = desc1 + cat_w2 @ relu(bnorm1d(g1)) + cat_b2 ------
__global__ void k_out(const float* __restrict__ d1,  const float* __restrict__ bng,
                      const float* __restrict__ bnb, const float* __restrict__ w2c,
                      const float* __restrict__ b2c, float* __restrict__ outp) {
    extern __shared__ float sm[];
    float* W = sm;            // 64*128
    float* G = sm + 8192;     // 128*32
    int n0 = blockIdx.x * 32;
    int tid = threadIdx.x;
    for (int i = tid; i < 8192; i += 256) W[i] = w2c[i];
    for (int i = tid; i < 4096; i += 256) {
        int o = i >> 5, c = i & 31;
        float x = g_g1[o * NN + n0 + c];
        float sc = rsqrtf(g_gstat[C2 + o] + 1e-5f) * bng[o];
        float v = fmaf(x - g_gstat[o], sc, bnb[o]);
        G[o * 32 + c] = fmaxf(v, 0.f);
    }
    __syncthreads();
    int colg = tid & 7, crow = (tid >> 3) * 2;
    int col0 = colg * 4;
    float a0[4], a1[4];
    float bb0 = b2c[crow], bb1 = b2c[crow + 1];
#pragma unroll
    for (int j = 0; j < 4; j++) { a0[j] = bb0; a1[j] = bb1; }
    for (int j = 0; j < 128; j++) {
        float4 x = *(float4*)&G[j * 32 + col0];
        float w0 = W[crow * 128 + j], w1 = W[(crow + 1) * 128 + j];
        a0[0] = fmaf(w0, x.x, a0[0]); a0[1] = fmaf(w0, x.y, a0[1]);
        a0[2] = fmaf(w0, x.z, a0[2]); a0[3] = fmaf(w0, x.w, a0[3]);
        a1[0] = fmaf(w1, x.x, a1[0]); a1[1] = fmaf(w1, x.y, a1[1]);
        a1[2] = fmaf(w1, x.z, a1[2]); a1[3] = fmaf(w1, x.w, a1[3]);
    }
    float4 dv0 = *(const float4*)&d1[crow * NN + n0 + col0];
    float4 dv1 = *(const float4*)&d1[(crow + 1) * NN + n0 + col0];
    *(float4*)&outp[crow * NN + n0 + col0] =
        make_float4(a0[0] + dv0.x, a0[1] + dv0.y, a0[2] + dv0.z, a0[3] + dv0.w);
    *(float4*)&outp[(crow + 1) * NN + n0 + col0] =
        make_float4(a1[0] + dv1.x, a1[1] + dv1.y, a1[2] + dv1.z, a1[3] + dv1.w);
}

// ---------------- launch ------------------------------------------------------
extern "C" void kernel_launch(void* const* d_in, const int* in_sizes, int n_in,
                              void* d_out, int out_size) {
    const float* desc1    = (const float*)d_in[0];
    const float* desc2    = (const float*)d_in[1];
    const float* qw       = (const float*)d_in[2];
    const float* qb       = (const float*)d_in[3];
    const float* kw       = (const float*)d_in[4];
    const float* kb       = (const float*)d_in[5];
    const float* vw       = (const float*)d_in[6];
    const float* vb       = (const float*)d_in[7];
    const float* mh_w     = (const float*)d_in[8];
    const float* mh_b     = (const float*)d_in[9];
    const float* cat_w1   = (const float*)d_in[10];
    const float* cat_b1   = (const float*)d_in[11];
    const float* cat_bn_g = (const float*)d_in[12];
    const float* cat_bn_b = (const float*)d_in[13];
    const float* cat_w2   = (const float*)d_in[14];
    const float* cat_b2   = (const float*)d_in[15];
    const float* shot_w   = (const float*)d_in[16];
    const float* shot_b   = (const float*)d_in[17];
    const float* bn1g     = (const float*)d_in[18];
    const float* bn1b     = (const float*)d_in[19];
    const float* sep_w1   = (const float*)d_in[20];
    // d_in[21] = sep_b1: cancels exactly in the second instance norm
    const float* bn2g     = (const float*)d_in[22];
    const float* bn2b     = (const float*)d_in[23];
    const float* sep_w2   = (const float*)d_in[24];
    const float* sep_b2   = (const float*)d_in[25];
    float* out_desc  = (float*)d_out;                 // [1,64,768]
    float* out_score = (float*)d_out + CC * NN;       // [1,768,768]

    const int HEAVY_SMEM = (8192 + 8192 + 128 * 4 + 64 * 2) * 4;   // 68096 B
    const int AV_SMEM    = (16 * 193 + 64 * 193) * 4;              // 61760 B
    const int CAT_SMEM   = (8192 + 4096) * 4;                      // 49152 B
    cudaFuncSetAttribute(k_heavy, cudaFuncAttributeMaxDynamicSharedMemorySize, HEAVY_SMEM);
    cudaFuncSetAttribute(k_av,    cudaFuncAttributeMaxDynamicSharedMemorySize, AV_SMEM);
    cudaFuncSetAttribute(k_cat1,  cudaFuncAttributeMaxDynamicSharedMemorySize, CAT_SMEM);
    cudaFuncSetAttribute(k_out,   cudaFuncAttributeMaxDynamicSharedMemorySize, CAT_SMEM);

    k_qkv    <<<dim3(12, 3), 256>>>(desc1, desc2, qw, qb, kw, kb, vw, vb);
    k_norm1  <<<128, 256>>>(bn1g, bn1b);
    k_AB     <<<dim3(12, 3), 256>>>(sep_w1, shot_w);
    k_rowstat<<<256, 256>>>();
    k_heavy  <<<dim3(12, 12), 256, HEAVY_SMEM>>>(bn2g, bn2b, sep_w2, sep_b2, shot_b);
    k_softmax<<<768, 256>>>(out_score);
    k_av     <<<dim3(48, 4), 256, AV_SMEM>>>(out_score);
    k_mh     <<<24, 256>>>(mh_w, mh_b);
    k_cat1   <<<dim3(24, 2), 256, CAT_SMEM>>>(desc1, cat_w1, cat_b1);
    k_gstat  <<<128, 256>>>();
    k_out    <<<24, 256, CAT_SMEM>>>(desc1, cat_bn_g, cat_bn_b, cat_w2, cat_b2, out_desc);
}

// round 10
// speedup vs baseline: 1.0488x; 1.0488x over previous
#include <cuda_runtime.h>

#define NN 768
#define CC 64
#define C2 128

// ---------------- scratch (device globals; no allocation allowed) -------------
__device__ float g_q[CC * NN], g_k[CC * NN], g_v[CC * NN];
__device__ float g_r1[C2 * NN];                 // relu(norm(q|k)) stacked
__device__ float g_A[C2 * NN], g_B[C2 * NN];    // separable conv1 outputs
__device__ float g_Sq[NN], g_Sk[NN];            // shortcut row/col terms
__device__ float g_psA[C2 * 12 * 2];            // per-tile (sum,sumsq) of A rows
__device__ float g_psB[C2 * 12 * 2];            // per-tile (sum,sumsq) of B rows
__device__ float g_P[NN * NN];                  // logits scratch
__device__ float g_avp[4 * CC * NN];            // split-k partials of score@v^T
__device__ float g_g1[C2 * NN];                 // cat conv1 output
__device__ float g_pg1[C2 * 48 * 2];            // per-tile (sum,sumsq) of g1 rows

// ---------------- reductions --------------------------------------------------
__device__ __forceinline__ float2 block_reduce_sum2(float a, float b) {
    __shared__ float sA[8], sB[8];
    __syncthreads();
#pragma unroll
    for (int o = 16; o > 0; o >>= 1) {
        a += __shfl_down_sync(0xffffffffu, a, o);
        b += __shfl_down_sync(0xffffffffu, b, o);
    }
    int lane = threadIdx.x & 31, w = threadIdx.x >> 5;
    if (lane == 0) { sA[w] = a; sB[w] = b; }
    __syncthreads();
    if (threadIdx.x == 0) {
        float ra = 0.f, rb = 0.f;
        int nw = blockDim.x >> 5;
        for (int i = 0; i < nw; i++) { ra += sA[i]; rb += sB[i]; }
        sA[0] = ra; sB[0] = rb;
    }
    __syncthreads();
    return make_float2(sA[0], sB[0]);
}

__device__ __forceinline__ float block_reduce_max(float a) {
    __shared__ float sM[8];
    __syncthreads();
#pragma unroll
    for (int o = 16; o > 0; o >>= 1)
        a = fmaxf(a, __shfl_down_sync(0xffffffffu, a, o));
    int lane = threadIdx.x & 31, w = threadIdx.x >> 5;
    if (lane == 0) sM[w] = a;
    __syncthreads();
    if (threadIdx.x == 0) {
        float r = sM[0];
        int nw = blockDim.x >> 5;
        for (int i = 1; i < nw; i++) r = fmaxf(r, sM[i]);
        sM[0] = r;
    }
    __syncthreads();
    return sM[0];
}

// ---------------- K1: q,k,v conv + fused inorm/bnorm/relu for q,k -------------
// grid = 48: tensor t = bx/16 (0=q,1=k,2=v), 4 channels per block, full 768 cols
__global__ void k_qkvn(const float* __restrict__ d1, const float* __restrict__ d2,
                       const float* __restrict__ qw, const float* __restrict__ qb,
                       const float* __restrict__ kw, const float* __restrict__ kb,
                       const float* __restrict__ vw, const float* __restrict__ vb,
                       const float* __restrict__ bn1g, const float* __restrict__ bn1b) {
    __shared__ float Ws[256];
    int bx = blockIdx.x;
    int t = bx >> 4, c0 = (bx & 15) * 4;
    const float* W    = t == 0 ? qw : (t == 1 ? kw : vw);
    const float* bias = t == 0 ? qb : (t == 1 ? kb : vb);
    const float* X    = t == 0 ? d1 : d2;
    float* outp       = t == 0 ? g_q : (t == 1 ? g_k : g_v);
    int tid = threadIdx.x;
    Ws[tid] = W[(c0 + (tid >> 6)) * 64 + (tid & 63)];
    __syncthreads();
    float acc[4][3];
#pragma unroll
    for (int ch = 0; ch < 4; ch++)
#pragma unroll
        for (int j = 0; j < 3; j++) acc[ch][j] = 0.f;
#pragma unroll 4
    for (int ci = 0; ci < 64; ci++) {
        float x0 = X[ci * NN + tid];
        float x1 = X[ci * NN + tid + 256];
        float x2 = X[ci * NN + tid + 512];
#pragma unroll
        for (int ch = 0; ch < 4; ch++) {
            float w = Ws[ch * 64 + ci];
            acc[ch][0] = fmaf(w, x0, acc[ch][0]);
            acc[ch][1] = fmaf(w, x1, acc[ch][1]);
            acc[ch][2] = fmaf(w, x2, acc[ch][2]);
        }
    }
#pragma unroll
    for (int ch = 0; ch < 4; ch++) {
        float bb = bias[c0 + ch];
        acc[ch][0] += bb; acc[ch][1] += bb; acc[ch][2] += bb;
        outp[(c0 + ch) * NN + tid]       = acc[ch][0];
        outp[(c0 + ch) * NN + tid + 256] = acc[ch][1];
        outp[(c0 + ch) * NN + tid + 512] = acc[ch][2];
    }
    if (t < 2) {
#pragma unroll
        for (int ch = 0; ch < 4; ch++) {
            float s  = acc[ch][0] + acc[ch][1] + acc[ch][2];
            float ss = acc[ch][0] * acc[ch][0] + acc[ch][1] * acc[ch][1]
                     + acc[ch][2] * acc[ch][2];
            float2 r = block_reduce_sum2(s, ss);
            float mean = r.x * (1.f / NN);
            float var  = r.y * (1.f / NN) - mean * mean;
            float rin  = rsqrtf(var + 1e-3f);                 // inorm2d eps
            float s2   = rsqrtf(var * rin * rin + 1e-5f);     // bnorm2d eps
            int gc = t * 64 + c0 + ch;
            float a = rin * s2 * bn1g[gc];
            float b = bn1b[gc] - mean * a;
            g_r1[gc * NN + tid]       = fmaxf(fmaf(a, acc[ch][0], b), 0.f);
            g_r1[gc * NN + tid + 256] = fmaxf(fmaf(a, acc[ch][1], b), 0.f);
            g_r1[gc * NN + tid + 512] = fmaxf(fmaf(a, acc[ch][2], b), 0.f);
        }
    }
}

// ---------------- K2: A/B GEMMs + per-tile stat partials + shortcut -----------
__global__ void k_AB(const float* __restrict__ w1, const float* __restrict__ shotw) {
    int g = blockIdx.y;
    int n0 = blockIdx.x * 64;
    int tid = threadIdx.x;
    if (g == 2) {  // Sq[n] = sum_c sw[c] q[c,n]; Sk[m] = sum_c sw[64+c] k[c,m]
        if (tid < 128) {
            int half = tid >> 6;
            int col  = tid & 63;
            const float* src = half ? g_k : g_q;
            const float* w   = shotw + half * 64;
            float s = 0.f;
            for (int c2 = 0; c2 < 64; c2++)
                s = fmaf(w[c2], src[c2 * NN + n0 + col], s);
            (half ? g_Sk : g_Sq)[n0 + col] = s;
        }
        return;
    }
    __shared__ float Wh[128 * 64];
    __shared__ float Xt[64 * 64];
    const float* r1src = g_r1 + g * 64 * NN;
    for (int i = tid; i < 8192; i += 256)
        Wh[i] = w1[(i >> 6) * 128 + g * 64 + (i & 63)];
    for (int i = tid; i < 4096; i += 256)
        Xt[i] = r1src[(i >> 6) * NN + n0 + (i & 63)];
    __syncthreads();
    int cg = tid & 15, orow = (tid >> 4) * 8;
    int col0 = cg * 4;
    float acc[8][4];
#pragma unroll
    for (int a = 0; a < 8; a++)
#pragma unroll
        for (int b = 0; b < 4; b++) acc[a][b] = 0.f;
    for (int i = 0; i < 64; i++) {
        float4 x = *(float4*)&Xt[i * 64 + col0];
#pragma unroll
        for (int oo = 0; oo < 8; oo++) {
            float w = Wh[(orow + oo) * 64 + i];
            acc[oo][0] = fmaf(w, x.x, acc[oo][0]);
            acc[oo][1] = fmaf(w, x.y, acc[oo][1]);
            acc[oo][2] = fmaf(w, x.z, acc[oo][2]);
            acc[oo][3] = fmaf(w, x.w, acc[oo][3]);
        }
    }
    float* out = g ? g_B : g_A;
#pragma unroll
    for (int oo = 0; oo < 8; oo++)
        *(float4*)&out[(orow + oo) * NN + n0 + col0] =
            make_float4(acc[oo][0], acc[oo][1], acc[oo][2], acc[oo][3]);
    // per-tile stat partials (reuse Wh as staging; all Wh reads are done)
    float* ps  = Wh;            // 128 x 16
    float* pss = Wh + 2048;     // 128 x 16
    __syncthreads();
#pragma unroll
    for (int oo = 0; oo < 8; oo++) {
        float s  = acc[oo][0] + acc[oo][1] + acc[oo][2] + acc[oo][3];
        float ss = acc[oo][0] * acc[oo][0] + acc[oo][1] * acc[oo][1]
                 + acc[oo][2] * acc[oo][2] + acc[oo][3] * acc[oo][3];
        ps [(orow + oo) * 16 + cg] = s;
        pss[(orow + oo) * 16 + cg] = ss;
    }
    __syncthreads();
    if (tid < 128) {
        float s = 0.f, ss = 0.f;
#pragma unroll
        for (int j = 0; j < 16; j++) { s += ps[tid * 16 + j]; ss += pss[tid * 16 + j]; }
        float* dst = g ? g_psB : g_psA;
        dst[(tid * 12 + blockIdx.x) * 2]     = s;
        dst[(tid * 12 + blockIdx.x) * 2 + 1] = ss;
    }
}

// ---------------- K3: heavy — P[n,m] = sum_o w2[o]*relu(A''+B') + row + col ---
__global__ void k_heavy(const float* __restrict__ bn2g, const float* __restrict__ bn2b,
                        const float* __restrict__ w2,   const float* __restrict__ b2,
                        const float* __restrict__ shotb) {
    extern __shared__ float sm[];
    float* As   = sm;             // 128*64
    float* Bs   = sm + 8192;      // 128*64
    float* tO   = sm + 16384;     // 128
    float* shA  = tO + 128;
    float* shB  = shA + 128;
    float* w2s  = shB + 128;
    float* rowc = w2s + 128;      // 64
    float* colc = rowc + 64;      // 64
    int tid = threadIdx.x;
    int n0 = blockIdx.x * 64, m0 = blockIdx.y * 64;
    if (tid < 128) {
        int o = tid;
        float sA = 0.f, ssA = 0.f, sB = 0.f, ssB = 0.f;
#pragma unroll
        for (int j = 0; j < 12; j++) {
            sA  += g_psA[(o * 12 + j) * 2];
            ssA += g_psA[(o * 12 + j) * 2 + 1];
            sB  += g_psB[(o * 12 + j) * 2];
            ssB += g_psB[(o * 12 + j) * 2 + 1];
        }
        float mA = sA * (1.f / NN), vA = ssA * (1.f / NN) - mA * mA;
        float mB = sB * (1.f / NN), vB = ssB * (1.f / NN) - mB * mB;
        float var = vA + vB;                          // exact for separable field
        float r2 = rsqrtf(var + 1e-3f);
        float t = r2 * rsqrtf(var * r2 * r2 + 1e-5f) * bn2g[o];
        tO[o]  = t;
        shA[o] = bn2b[o] - mA * t;
        shB[o] = -mB * t;
        w2s[o] = w2[o];
    } else if (tid < 192) {
        int i = tid - 128;
        rowc[i] = g_Sq[n0 + i] + b2[0] + shotb[0];
    } else {
        int i = tid - 192;
        colc[i] = g_Sk[m0 + i];
    }
    __syncthreads();
    for (int idx = tid; idx < 2048; idx += 256) {
        int o = idx >> 4, c = (idx & 15) * 4;
        float t = tO[o];
        float sA = shA[o], sB = shB[o];
        float4 a = *(const float4*)&g_A[o * NN + n0 + c];
        a.x = fmaf(a.x, t, sA); a.y = fmaf(a.y, t, sA);
        a.z = fmaf(a.z, t, sA); a.w = fmaf(a.w, t, sA);
        *(float4*)&As[o * 64 + c] = a;
        float4 b = *(const float4*)&g_B[o * NN + m0 + c];
        b.x = fmaf(b.x, t, sB); b.y = fmaf(b.y, t, sB);
        b.z = fmaf(b.z, t, sB); b.w = fmaf(b.w, t, sB);
        *(float4*)&Bs[o * 64 + c] = b;
    }
    __syncthreads();
    int tn = tid & 15, tm = tid >> 4;
    int na = tn * 4, ma = tm * 4;
    float acc[16];
#pragma unroll
    for (int i = 0; i < 16; i++) acc[i] = 0.f;
#pragma unroll 2
    for (int o = 0; o < 128; o++) {
        float4 af = *(float4*)&As[o * 64 + na];
        float4 bf = *(float4*)&Bs[o * 64 + ma];
        float w = w2s[o];
        float av[4] = {af.x, af.y, af.z, af.w};
        float bv[4] = {bf.x, bf.y, bf.z, bf.w};
#pragma unroll
        for (int i = 0; i < 4; i++)
#pragma unroll
            for (int j = 0; j < 4; j++)
                acc[i * 4 + j] = fmaf(w, fmaxf(av[i] + bv[j], 0.f), acc[i * 4 + j]);
    }
#pragma unroll
    for (int i = 0; i < 4; i++) {
        float rc = rowc[na + i];
        float4 o4;
        o4.x = acc[i * 4 + 0] + rc + colc[ma + 0];
        o4.y = acc[i * 4 + 1] + rc + colc[ma + 1];
        o4.z = acc[i * 4 + 2] + rc + colc[ma + 2];
        o4.w = acc[i * 4 + 3] + rc + colc[ma + 3];
        *(float4*)&g_P[(n0 + na + i) * NN + m0 + ma] = o4;
    }
}

// ---------------- K4: row softmax --------------------------------------------
__global__ void k_softmax(float* __restrict__ score) {
    __shared__ float row[NN];
    int n = blockIdx.x;
    int tid = threadIdx.x;
    float mx = -1e30f;
    for (int i = tid; i < NN; i += 256) { float v = g_P[n * NN + i]; row[i] = v; mx = fmaxf(mx, v); }
    mx = block_reduce_max(mx);
    float s = 0.f;
    for (int i = tid; i < NN; i += 256) { float e = __expf(row[i] - mx); row[i] = e; s += e; }
    float2 rr = block_reduce_sum2(s, 0.f);
    float inv = 1.f / rr.x;
    for (int i = tid; i < NN; i += 256) score[n * NN + i] = row[i] * inv;
}

// ---------------- K5: av[d,n] = sum_m score[n,m] v[d,m] (split-k partials) ----
__global__ void k_av(const float* __restrict__ score) {
    extern __shared__ float sm[];
    float* Ss = sm;                 // 16*193
    float* Vs = sm + 16 * 193;      // 64*193
    int n0 = blockIdx.x * 16;
    int m0 = blockIdx.y * 192;
    int tid = threadIdx.x;
    for (int idx = tid; idx < 16 * 192; idx += 256) {
        int n = idx / 192, m = idx - n * 192;
        Ss[n * 193 + m] = score[(n0 + n) * NN + m0 + m];
    }
    for (int idx = tid; idx < 64 * 192; idx += 256) {
        int d = idx / 192, m = idx - d * 192;
        Vs[d * 193 + m] = g_v[d * NN + m0 + m];
    }
    __syncthreads();
    int nl = tid & 15, dg = tid >> 4;
    float a0 = 0.f, a1 = 0.f, a2 = 0.f, a3 = 0.f;
    const float* sp = &Ss[nl * 193];
    const float* vp = &Vs[dg * 4 * 193];
    for (int m = 0; m < 192; m++) {
        float s = sp[m];
        a0 = fmaf(vp[m], s, a0);
        a1 = fmaf(vp[193 + m], s, a1);
        a2 = fmaf(vp[2 * 193 + m], s, a2);
        a3 = fmaf(vp[3 * 193 + m], s, a3);
    }
    int d0 = dg * 4;
    float* out = g_avp + blockIdx.y * CC * NN;
    out[(d0 + 0) * NN + n0 + nl] = a0;
    out[(d0 + 1) * NN + n0 + nl] = a1;
    out[(d0 + 2) * NN + n0 + nl] = a2;
    out[(d0 + 3) * NN + n0 + nl] = a3;
}

// ---------------- K6: fused avp-reduce + mh conv + cat conv1 + g1 stats -------
// grid = 48 blocks x 16-col tiles, 256 threads
__global__ void k_cat(const float* __restrict__ d1,
                      const float* __restrict__ mhw, const float* __restrict__ mhb,
                      const float* __restrict__ w1c, const float* __restrict__ b1c) {
    extern __shared__ float sm[];
    float* Wc  = sm;                    // 128*128
    float* Wm  = Wc + 16384;            // 64*64
    float* Xc  = Wm + 4096;             // 128*16 (top=desc1, bottom=av2)
    float* avt = Xc + 2048;             // 64*16
    float* ps  = avt + 1024;            // 128*4
    float* pss = ps + 512;              // 128*4
    int n0 = blockIdx.x * 16;
    int tid = threadIdx.x;
    for (int i = tid; i < 16384; i += 256) Wc[i] = w1c[i];
    for (int i = tid; i < 4096; i += 256)  Wm[i] = mhw[i];
    for (int i = tid; i < 1024; i += 256) {
        int d = i >> 4, c = i & 15;
        float v = 0.f;
#pragma unroll
        for (int s = 0; s < 4; s++) v += g_avp[(s * 64 + d) * NN + n0 + c];
        avt[i] = v;
        Xc[i] = d1[d * NN + n0 + c];    // rows 0..63 of cat input
    }
    __syncthreads();
    // mh: av2 = Wm @ avt + mhb  -> Xc rows 64..127
    {
        int row = tid >> 2, c0 = (tid & 3) * 4;
        float a0 = mhb[row], a1 = a0, a2 = a0, a3 = a0;
        for (int d = 0; d < 64; d++) {
            float w = Wm[row * 64 + d];
            float4 x = *(float4*)&avt[d * 16 + c0];
            a0 = fmaf(w, x.x, a0); a1 = fmaf(w, x.y, a1);
            a2 = fmaf(w, x.z, a2); a3 = fmaf(w, x.w, a3);
        }
        *(float4*)&Xc[(64 + row) * 16 + c0] = make_float4(a0, a1, a2, a3);
    }
    __syncthreads();
    // cat conv1: g1 = Wc @ Xc + b1c, 2 rows x 4 cols per thread
    {
        int r0 = (tid >> 2) * 2, c0 = (tid & 3) * 4;
        float a0[4], a1[4];
        float bb0 = b1c[r0], bb1 = b1c[r0 + 1];
#pragma unroll
        for (int j = 0; j < 4; j++) { a0[j] = bb0; a1[j] = bb1; }
        for (int j = 0; j < 128; j++) {
            float4 x = *(float4*)&Xc[j * 16 + c0];
            float w0 = Wc[r0 * 128 + j], w1 = Wc[(r0 + 1) * 128 + j];
            a0[0] = fmaf(w0, x.x, a0[0]); a0[1] = fmaf(w0, x.y, a0[1]);
            a0[2] = fmaf(w0, x.z, a0[2]); a0[3] = fmaf(w0, x.w, a0[3]);
            a1[0] = fmaf(w1, x.x, a1[0]); a1[1] = fmaf(w1, x.y, a1[1]);
            a1[2] = fmaf(w1, x.z, a1[2]); a1[3] = fmaf(w1, x.w, a1[3]);
        }
        *(float4*)&g_g1[r0 * NN + n0 + c0]       = make_float4(a0[0], a0[1], a0[2], a0[3]);
        *(float4*)&g_g1[(r0 + 1) * NN + n0 + c0] = make_float4(a1[0], a1[1], a1[2], a1[3]);
        // stat partials
        int cg = tid & 3;
        ps [r0 * 4 + cg] = a0[0] + a0[1] + a0[2] + a0[3];
        pss[r0 * 4 + cg] = a0[0]*a0[0] + a0[1]*a0[1] + a0[2]*a0[2] + a0[3]*a0[3];
        ps [(r0 + 1) * 4 + cg] = a1[0] + a1[1] + a1[2] + a1[3];
        pss[(r0 + 1) * 4 + cg] = a1[0]*a1[0] + a1[1]*a1[1] + a1[2]*a1[2] + a1[3]*a1[3];
    }
    __syncthreads();
    if (tid < 128) {
        float s = ps[tid*4] + ps[tid*4+1] + ps[tid*4+2] + ps[tid*4+3];
        float q = pss[tid*4] + pss[tid*4+1] + pss[tid*4+2] + pss[tid*4+3];
        g_pg1[(tid * 48 + blockIdx.x) * 2]     = s;
        g_pg1[(tid * 48 + blockIdx.x) * 2 + 1] = q;
    }
}

// ---------------- K7: gstat-reduce + bnorm1d relu + cat conv2 + residual ------
__global__ void k_out(const float* __restrict__ d1,  const float* __restrict__ bng,
                      const float* __restrict__ bnb, const float* __restrict__ w2c,
                      const float* __restrict__ b2c, float* __restrict__ outp) {
    extern __shared__ float sm[];
    float* W = sm;            // 64*128
    float* G = sm + 8192;     // 128*32
    __shared__ float affA[128], affB[128];
    int n0 = blockIdx.x * 32;
    int tid = threadIdx.x;
    if (tid < 128) {
        float s = 0.f, q = 0.f;
#pragma unroll 8
        for (int j = 0; j < 48; j++) {
            s += g_pg1[(tid * 48 + j) * 2];
            q += g_pg1[(tid * 48 + j) * 2 + 1];
        }
        float mean = s * (1.f / NN);
        float var  = q * (1.f / NN) - mean * mean;
        float a = rsqrtf(var + 1e-5f) * bng[tid];
        affA[tid] = a;
        affB[tid] = bnb[tid] - mean * a;
    }
    for (int i = tid; i < 8192; i += 256) W[i] = w2c[i];
    __syncthreads();
    for (int i = tid; i < 4096; i += 256) {
        int o = i >> 5, c = i & 31;
        float x = g_g1[o * NN + n0 + c];
        G[o * 32 + c] = fmaxf(fmaf(affA[o], x, affB[o]), 0.f);
    }
    __syncthreads();
    int colg = tid & 7, crow = (tid >> 3) * 2;
    int col0 = colg * 4;
    float a0[4], a1[4];
    float bb0 = b2c[crow], bb1 = b2c[crow + 1];
#pragma unroll
    for (int j = 0; j < 4; j++) { a0[j] = bb0; a1[j] = bb1; }
    for (int j = 0; j < 128; j++) {
        float4 x = *(float4*)&G[j * 32 + col0];
        float w0 = W[crow * 128 + j], w1 = W[(crow + 1) * 128 + j];
        a0[0] = fmaf(w0, x.x, a0[0]); a0[1] = fmaf(w0, x.y, a0[1]);
        a0[2] = fmaf(w0, x.z, a0[2]); a0[3] = fmaf(w0, x.w, a0[3]);
        a1[0] = fmaf(w1, x.x, a1[0]); a1[1] = fmaf(w1, x.y, a1[1]);
        a1[2] = fmaf(w1, x.z, a1[2]); a1[3] = fmaf(w1, x.w, a1[3]);
    }
    float4 dv0 = *(const float4*)&d1[crow * NN + n0 + col0];
    float4 dv1 = *(const float4*)&d1[(crow + 1) * NN + n0 + col0];
    *(float4*)&outp[crow * NN + n0 + col0] =
        make_float4(a0[0] + dv0.x, a0[1] + dv0.y, a0[2] + dv0.z, a0[3] + dv0.w);
    *(float4*)&outp[(crow + 1) * NN + n0 + col0] =
        make_float4(a1[0] + dv1.x, a1[1] + dv1.y, a1[2] + dv1.z, a1[3] + dv1.w);
}

// ---------------- launch ------------------------------------------------------
extern "C" void kernel_launch(void* const* d_in, const int* in_sizes, int n_in,
                              void* d_out, int out_size) {
    const float* desc1    = (const float*)d_in[0];
    const float* desc2    = (const float*)d_in[1];
    const float* qw       = (const float*)d_in[2];
    const float* qb       = (const float*)d_in[3];
    const float* kw       = (const float*)d_in[4];
    const float* kb       = (const float*)d_in[5];
    const float* vw       = (const float*)d_in[6];
    const float* vb       = (const float*)d_in[7];
    const float* mh_w     = (const float*)d_in[8];
    const float* mh_b     = (const float*)d_in[9];
    const float* cat_w1   = (const float*)d_in[10];
    const float* cat_b1   = (const float*)d_in[11];
    const float* cat_bn_g = (const float*)d_in[12];
    const float* cat_bn_b = (const float*)d_in[13];
    const float* cat_w2   = (const float*)d_in[14];
    const float* cat_b2   = (const float*)d_in[15];
    const float* shot_w   = (const float*)d_in[16];
    const float* shot_b   = (const float*)d_in[17];
    const float* bn1g     = (const float*)d_in[18];
    const float* bn1b     = (const float*)d_in[19];
    const float* sep_w1   = (const float*)d_in[20];
    // d_in[21] = sep_b1: cancels exactly in the second instance norm
    const float* bn2g     = (const float*)d_in[22];
    const float* bn2b     = (const float*)d_in[23];
    const float* sep_w2   = (const float*)d_in[24];
    const float* sep_b2   = (const float*)d_in[25];
    float* out_desc  = (float*)d_out;                 // [1,64,768]
    float* out_score = (float*)d_out + CC * NN;       // [1,768,768]

    const int HEAVY_SMEM = (8192 + 8192 + 128 * 4 + 64 * 2) * 4;       // 68096 B
    const int AV_SMEM    = (16 * 193 + 64 * 193) * 4;                  // 61760 B
    const int CAT_SMEM   = (16384 + 4096 + 2048 + 1024 + 512 + 512) * 4; // 98304 B
    const int OUT_SMEM   = (8192 + 4096) * 4;                          // 49152 B
    cudaFuncSetAttribute(k_heavy, cudaFuncAttributeMaxDynamicSharedMemorySize, HEAVY_SMEM);
    cudaFuncSetAttribute(k_av,    cudaFuncAttributeMaxDynamicSharedMemorySize, AV_SMEM);
    cudaFuncSetAttribute(k_cat,   cudaFuncAttributeMaxDynamicSharedMemorySize, CAT_SMEM);
    cudaFuncSetAttribute(k_out,   cudaFuncAttributeMaxDynamicSharedMemorySize, OUT_SMEM);

    k_qkvn   <<<48, 256>>>(desc1, desc2, qw, qb, kw, kb, vw, vb, bn1g, bn1b);
    k_AB     <<<dim3(12, 3), 256>>>(sep_w1, shot_w);
    k_heavy  <<<dim3(12, 12), 256, HEAVY_SMEM>>>(bn2g, bn2b, sep_w2, sep_b2, shot_b);
    k_softmax<<<768, 256>>>(out_score);
    k_av     <<<dim3(48, 4), 256, AV_SMEM>>>(out_score);
    k_cat    <<<48, 256, CAT_SMEM>>>(desc1, mh_w, mh_b, cat_w1, cat_b1);
    k_out    <<<24, 256, OUT_SMEM>>>(desc1, cat_bn_g, cat_bn_b, cat_w2, cat_b2, out_desc);
}